// round 2
// baseline (speedup 1.0000x reference)
#include <cuda_runtime.h>

// ContinuousCRF: 5 mean-field iterations of an 80-tap disk stencil (radius 5,
// weight exp(-dist)) + 3x3 compatibility mix + channel softmax, on a 96x96
// grid with C=3 channels. Five fused kernel launches (iteration 1 computes
// q0 = softmax(unary) on the fly), ping-ponging a float4-packed q buffer
// through __device__ scratch.

#define HH 96
#define WW 96
#define NPIX (HH * WW)
#define ROWS_PER_CTA 2
#define HALO 5
#define TW (WW + 2 * HALO)               // 106 smem columns (x zero-pad built in)
#define SROWS (ROWS_PER_CTA + 2 * HALO)  // 12 smem rows
#define NTHREADS (WW * ROWS_PER_CTA)     // 192
#define NBLOCKS (HH / ROWS_PER_CTA)      // 48
#define WLUT 121                         // 11x11 tap-weight LUT

// Ping-pong q buffers, packed (q0,q1,q2,0) per pixel.
__device__ float4 g_q[2][NPIX];

template <bool FIRST, bool LAST>
__global__ __launch_bounds__(NTHREADS)
void crf_iter(const float* __restrict__ unary,
              const float* __restrict__ comp,
              float* __restrict__ out,
              int srcbuf)
{
    __shared__ float4 s_q[SROWS * TW];
    __shared__ float  s_w[WLUT];

    const int tid = threadIdx.x;

    // Per-CTA tap-weight LUT: w[(dy+5)*11+(dx+5)] = exp(-dist), 0 on diagonal
    // and outside the radius-5 disk (those entries are never read anyway —
    // the tap loop below skips them at compile time).
    if (tid < WLUT) {
        const int dy = tid / 11 - 5;
        const int dx = tid % 11 - 5;
        const int d2 = dy * dy + dx * dx;
        s_w[tid] = (d2 > 0 && d2 <= 25) ? expf(-sqrtf((float)d2)) : 0.f;
    }

    const int y0 = blockIdx.x * ROWS_PER_CTA;
    const float4* __restrict__ qs = g_q[srcbuf];

    // Halo fill (zero-padded outside the image). In the FIRST iteration,
    // compute q0 = softmax(unary) on the fly instead of reading g_q.
    for (int i = tid; i < SROWS * TW; i += NTHREADS) {
        const int r  = i / TW;
        const int cc = i - r * TW;
        const int gy = y0 - HALO + r;
        const int gx = cc - HALO;
        float4 v = make_float4(0.f, 0.f, 0.f, 0.f);
        if (gy >= 0 && gy < HH && gx >= 0 && gx < WW) {
            const int n = gy * WW + gx;
            if (FIRST) {
                float u0 = unary[n];
                float u1 = unary[NPIX + n];
                float u2 = unary[2 * NPIX + n];
                float mx = fmaxf(u0, fmaxf(u1, u2));
                float e0 = expf(u0 - mx), e1 = expf(u1 - mx), e2 = expf(u2 - mx);
                float rs = 1.f / (e0 + e1 + e2);
                v = make_float4(e0 * rs, e1 * rs, e2 * rs, 0.f);
            } else {
                v = qs[n];
            }
        }
        s_q[i] = v;
    }
    __syncthreads();

    // One output pixel per thread.
    const int x  = tid % WW;
    const int yl = tid / WW;
    const int gy = y0 + yl;
    const int n  = gy * WW + x;
    const int center = (yl + HALO) * TW + (x + HALO);

    float m0 = 0.f, m1 = 0.f, m2 = 0.f;
#pragma unroll
    for (int dy = -5; dy <= 5; dy++) {
#pragma unroll
        for (int dx = -5; dx <= 5; dx++) {
            // These conditions involve only unrolled loop constants:
            // invalid taps vanish at compile time (80 survive).
            if (dy * dy + dx * dx == 0) continue;
            if (dy * dy + dx * dx > 25) continue;
            const float  w = s_w[(dy + 5) * 11 + (dx + 5)];
            const float4 v = s_q[center + dy * TW + dx];
            m0 = fmaf(w, v.x, m0);
            m1 = fmaf(w, v.y, m1);
            m2 = fmaf(w, v.z, m2);
        }
    }

    // 3x3 compatibility mix (general matrix; identity in this instance).
    const float cm0 = comp[0] * m0 + comp[1] * m1 + comp[2] * m2;
    const float cm1 = comp[3] * m0 + comp[4] * m1 + comp[5] * m2;
    const float cm2 = comp[6] * m0 + comp[7] * m1 + comp[8] * m2;

    // logits = (unary + comp_msg) / TEMP, TEMP = 1.
    const float l0 = unary[n]            + cm0;
    const float l1 = unary[NPIX + n]     + cm1;
    const float l2 = unary[2 * NPIX + n] + cm2;

    const float mx = fmaxf(l0, fmaxf(l1, l2));
    float e0 = expf(l0 - mx), e1 = expf(l1 - mx), e2 = expf(l2 - mx);
    const float rs = 1.f / (e0 + e1 + e2);
    e0 *= rs; e1 *= rs; e2 *= rs;

    if (LAST) {
        out[n]            = e0;
        out[NPIX + n]     = e1;
        out[2 * NPIX + n] = e2;
    } else {
        g_q[srcbuf ^ 1][n] = make_float4(e0, e1, e2, 0.f);
    }
}

extern "C" void kernel_launch(void* const* d_in, const int* in_sizes, int n_in,
                              void* d_out, int out_size)
{
    (void)in_sizes; (void)n_in; (void)out_size;
    const float* unary = (const float*)d_in[0];
    const float* comp  = (const float*)d_in[1];
    float* out = (float*)d_out;

    // iter 1: softmax(unary) fused in, writes g_q[0]  (srcbuf=1 -> dst=0)
    crf_iter<true,  false><<<NBLOCKS, NTHREADS>>>(unary, comp, nullptr, 1);
    // iter 2: g_q[0] -> g_q[1]
    crf_iter<false, false><<<NBLOCKS, NTHREADS>>>(unary, comp, nullptr, 0);
    // iter 3: g_q[1] -> g_q[0]
    crf_iter<false, false><<<NBLOCKS, NTHREADS>>>(unary, comp, nullptr, 1);
    // iter 4: g_q[0] -> g_q[1]
    crf_iter<false, false><<<NBLOCKS, NTHREADS>>>(unary, comp, nullptr, 0);
    // iter 5: g_q[1] -> out
    crf_iter<false, true ><<<NBLOCKS, NTHREADS>>>(unary, comp, out, 1);
}

// round 3
// speedup vs baseline: 1.0734x; 1.0734x over previous
#include <cuda_runtime.h>

// ContinuousCRF, fully fused: ONE persistent kernel runs all 5 mean-field
// iterations. 96 CTAs (one image row each, all co-resident on 148 SMs),
// 384 threads = 4 threads/pixel each doing a compile-time quarter of the
// 80-tap radius-5 disk stencil. Iterations are separated by a hand-rolled
// atomic grid barrier; q ping-pongs through __device__ global scratch with
// L2-coherent (__ldcg) accesses.

#define HH 96
#define WW 96
#define NPIX (HH * WW)
#define HALO 5
#define TW (WW + 2 * HALO)     // 106 smem columns (x zero-pad built in)
#define SROWS (1 + 2 * HALO)   // 11 smem rows (1-row tile + halo)
#define NBLK HH                // 96 CTAs, one per row
#define NTY 4                  // threads per pixel
#define TPB (WW * NTY)         // 384 threads
#define WLUT 121               // 11x11 tap-weight LUT
#define NITER 5
#define TAPS_PER_GROUP 20      // 80 taps / 4 groups

// Ping-pong q buffers, packed (q0,q1,q2,0) per pixel.
__device__ float4 g_q[2][NPIX];

// Grid-barrier state (persists across graph replays; generation counter is
// monotonic so equality-polling stays correct).
__device__ unsigned g_bar_count = 0;
__device__ unsigned g_bar_gen   = 0;

__device__ __forceinline__ void grid_barrier(int tid)
{
    __syncthreads();
    if (tid == 0) {
        __threadfence();  // publish this CTA's g_q writes (also flushes L1D)
        unsigned my = *((volatile unsigned*)&g_bar_gen);
        unsigned a  = atomicAdd(&g_bar_count, 1u);
        if (a == NBLK - 1) {
            atomicExch(&g_bar_count, 0u);
            __threadfence();
            atomicAdd(&g_bar_gen, 1u);
        } else {
            while (*((volatile unsigned*)&g_bar_gen) == my) { }
        }
        __threadfence();  // acquire: other CTAs' writes visible below
    }
    __syncthreads();
}

// Accumulate taps [G*20, G*20+20) of the 80 valid (dy,dx) disk offsets.
// The enumeration counter t is resolved at compile time after full unroll,
// so each instantiation contains exactly 20 LDS.128 + 60 FMA.
template <int G>
__device__ __forceinline__ void accum(const float4* __restrict__ s_q,
                                      const float*  __restrict__ s_w,
                                      int center,
                                      float& m0, float& m1, float& m2)
{
    int t = 0;
#pragma unroll
    for (int dy = -5; dy <= 5; dy++) {
#pragma unroll
        for (int dx = -5; dx <= 5; dx++) {
            const int d2 = dy * dy + dx * dx;
            if (d2 == 0 || d2 > 25) continue;   // folds at compile time
            if (t >= G * TAPS_PER_GROUP && t < (G + 1) * TAPS_PER_GROUP) {
                const float  w = s_w[(dy + 5) * 11 + (dx + 5)];
                const float4 v = s_q[center + dy * TW + dx];
                m0 = fmaf(w, v.x, m0);
                m1 = fmaf(w, v.y, m1);
                m2 = fmaf(w, v.z, m2);
            }
            t++;
        }
    }
}

__global__ __launch_bounds__(TPB, 1)
void crf_all(const float* __restrict__ unary,
             const float* __restrict__ comp,
             float* __restrict__ out)
{
    __shared__ float4 s_q[SROWS * TW];
    __shared__ float  s_w[WLUT];
    __shared__ float  s_part[NTY - 1][3 * WW];   // partial sums from ty=1..3

    const int tid = threadIdx.x;
    const int x   = tid % WW;
    const int ty  = tid / WW;
    const int y   = blockIdx.x;
    const int n   = y * WW + x;

    // Tap-weight LUT: w = exp(-theta_beta * dist), theta_beta = 1.
    if (tid < WLUT) {
        const int dy = tid / 11 - 5;
        const int dx = tid % 11 - 5;
        const int d2 = dy * dy + dx * dx;
        s_w[tid] = (d2 > 0 && d2 <= 25) ? expf(-sqrtf((float)d2)) : 0.f;
    }

    // Compatibility matrix in registers (read-only, uniform).
    const float c00 = __ldg(comp + 0), c01 = __ldg(comp + 1), c02 = __ldg(comp + 2);
    const float c10 = __ldg(comp + 3), c11 = __ldg(comp + 4), c12 = __ldg(comp + 5);
    const float c20 = __ldg(comp + 6), c21 = __ldg(comp + 7), c22 = __ldg(comp + 8);

    // This pixel's unary logits (needed only by the epilogue threads).
    float u0 = 0.f, u1 = 0.f, u2 = 0.f;
    if (ty == 0) {
        u0 = __ldg(unary + n);
        u1 = __ldg(unary + NPIX + n);
        u2 = __ldg(unary + 2 * NPIX + n);
    }

    for (int it = 0; it < NITER; it++) {
        // ---- halo fill (zero-padded outside the image) ----
        const float4* __restrict__ qsrc = g_q[(it + 1) & 1];
        for (int i = tid; i < SROWS * TW; i += TPB) {
            const int r  = i / TW;
            const int cc = i - r * TW;
            const int gy = y - HALO + r;
            const int gx = cc - HALO;
            float4 v = make_float4(0.f, 0.f, 0.f, 0.f);
            if (gy >= 0 && gy < HH && gx >= 0 && gx < WW) {
                const int m = gy * WW + gx;
                if (it == 0) {
                    // q0 = softmax(unary) computed on the fly
                    const float a0 = __ldg(unary + m);
                    const float a1 = __ldg(unary + NPIX + m);
                    const float a2 = __ldg(unary + 2 * NPIX + m);
                    const float mx = fmaxf(a0, fmaxf(a1, a2));
                    const float e0 = expf(a0 - mx), e1 = expf(a1 - mx), e2 = expf(a2 - mx);
                    const float rs = 1.f / (e0 + e1 + e2);
                    v = make_float4(e0 * rs, e1 * rs, e2 * rs, 0.f);
                } else {
                    v = __ldcg(qsrc + m);   // L2-coherent (skip stale L1)
                }
            }
            s_q[i] = v;
        }
        __syncthreads();

        // ---- 80-tap stencil, split 4 ways across ty ----
        const int center = HALO * TW + (x + HALO);
        float m0 = 0.f, m1 = 0.f, m2 = 0.f;
        switch (ty) {
            case 0: accum<0>(s_q, s_w, center, m0, m1, m2); break;
            case 1: accum<1>(s_q, s_w, center, m0, m1, m2); break;
            case 2: accum<2>(s_q, s_w, center, m0, m1, m2); break;
            default: accum<3>(s_q, s_w, center, m0, m1, m2); break;
        }
        if (ty > 0) {
            s_part[ty - 1][0 * WW + x] = m0;
            s_part[ty - 1][1 * WW + x] = m1;
            s_part[ty - 1][2 * WW + x] = m2;
        }
        __syncthreads();

        // ---- epilogue: combine partials, compat mix, softmax, store ----
        if (ty == 0) {
            m0 += s_part[0][0 * WW + x] + s_part[1][0 * WW + x] + s_part[2][0 * WW + x];
            m1 += s_part[0][1 * WW + x] + s_part[1][1 * WW + x] + s_part[2][1 * WW + x];
            m2 += s_part[0][2 * WW + x] + s_part[1][2 * WW + x] + s_part[2][2 * WW + x];

            const float cm0 = c00 * m0 + c01 * m1 + c02 * m2;
            const float cm1 = c10 * m0 + c11 * m1 + c12 * m2;
            const float cm2 = c20 * m0 + c21 * m1 + c22 * m2;

            const float l0 = u0 + cm0;
            const float l1 = u1 + cm1;
            const float l2 = u2 + cm2;

            const float mx = fmaxf(l0, fmaxf(l1, l2));
            float e0 = expf(l0 - mx), e1 = expf(l1 - mx), e2 = expf(l2 - mx);
            const float rs = 1.f / (e0 + e1 + e2);
            e0 *= rs; e1 *= rs; e2 *= rs;

            if (it == NITER - 1) {
                out[n]            = e0;
                out[NPIX + n]     = e1;
                out[2 * NPIX + n] = e2;
            } else {
                g_q[it & 1][n] = make_float4(e0, e1, e2, 0.f);
            }
        }

        if (it < NITER - 1) grid_barrier(tid);
    }
}

extern "C" void kernel_launch(void* const* d_in, const int* in_sizes, int n_in,
                              void* d_out, int out_size)
{
    (void)in_sizes; (void)n_in; (void)out_size;
    const float* unary = (const float*)d_in[0];
    const float* comp  = (const float*)d_in[1];
    float* out = (float*)d_out;

    crf_all<<<NBLK, TPB>>>(unary, comp, out);
}

// round 4
// speedup vs baseline: 1.2947x; 1.2061x over previous
#include <cuda_runtime.h>

// ContinuousCRF, fully fused persistent kernel, POINT-TO-POINT sync:
// 96 CTAs (one image row each), 384 threads = 4 threads/pixel, each doing a
// compile-time quarter of the 80-tap radius-5 disk stencil. Instead of a
// global grid barrier between iterations, each CTA publishes a monotonic
// per-row progress counter and only waits on its 10 neighbor rows (|dy|<=5)
// — dependencies propagate as a local wavefront. Counters are monotonic
// across graph replays (base recovered from own counter at entry).

#define HH 96
#define WW 96
#define NPIX (HH * WW)
#define HALO 5
#define TW (WW + 2 * HALO)     // 106 smem columns (x zero-pad built in)
#define SROWS (1 + 2 * HALO)   // 11 smem rows (1-row tile + halo)
#define NBLK HH                // 96 CTAs, one per row
#define NTY 4                  // threads per pixel
#define TPB (WW * NTY)         // 384 threads
#define WLUT 121               // 11x11 tap-weight LUT
#define NITER 5
#define TAPS_PER_GROUP 20      // 80 taps / 4 groups
#define FLAG_STRIDE 32         // one 128B L2 line per row flag

// Ping-pong q buffers, packed (q0,q1,q2,0) per pixel.
__device__ float4 g_q[2][NPIX];

// Per-row monotonic progress counters (iterations completed, cumulative
// across graph replays). Padded so each row owns its own L2 line.
__device__ unsigned g_done[HH * FLAG_STRIDE];

__device__ __forceinline__ unsigned ld_flag(const unsigned* p)
{
    unsigned v;
    asm volatile("ld.global.cg.u32 %0, [%1];" : "=r"(v) : "l"(p));
    return v;
}

// Accumulate taps [G*20, G*20+20) of the 80 valid (dy,dx) disk offsets.
// The enumeration counter t resolves at compile time after full unroll,
// so each instantiation is exactly 20 LDS.128 + 60 FMA.
template <int G>
__device__ __forceinline__ void accum(const float4* __restrict__ s_q,
                                      const float*  __restrict__ s_w,
                                      int center,
                                      float& m0, float& m1, float& m2)
{
    int t = 0;
#pragma unroll
    for (int dy = -5; dy <= 5; dy++) {
#pragma unroll
        for (int dx = -5; dx <= 5; dx++) {
            const int d2 = dy * dy + dx * dx;
            if (d2 == 0 || d2 > 25) continue;   // folds at compile time
            if (t >= G * TAPS_PER_GROUP && t < (G + 1) * TAPS_PER_GROUP) {
                const float  w = s_w[(dy + 5) * 11 + (dx + 5)];
                const float4 v = s_q[center + dy * TW + dx];
                m0 = fmaf(w, v.x, m0);
                m1 = fmaf(w, v.y, m1);
                m2 = fmaf(w, v.z, m2);
            }
            t++;
        }
    }
}

__global__ __launch_bounds__(TPB, 1)
void crf_all(const float* __restrict__ unary,
             const float* __restrict__ comp,
             float* __restrict__ out)
{
    __shared__ float4   s_q[SROWS * TW];
    __shared__ float    s_w[WLUT];
    __shared__ float4   s_part[NTY - 1][WW];   // partial sums from ty=1..3
    __shared__ unsigned s_base;

    const int tid = threadIdx.x;
    const int x   = tid % WW;
    const int ty  = tid / WW;
    const int y   = blockIdx.x;
    const int n   = y * WW + x;

    // Recover the per-replay base of the monotonic counters from our own flag
    // (we are the only writer of it; it advanced by NITER-1 last replay).
    if (tid == 0) s_base = ld_flag(&g_done[y * FLAG_STRIDE]);

    // Tap-weight LUT: w = exp(-theta_beta * dist), theta_beta = 1.
    if (tid < WLUT) {
        const int dy = tid / 11 - 5;
        const int dx = tid % 11 - 5;
        const int d2 = dy * dy + dx * dx;
        s_w[tid] = (d2 > 0 && d2 <= 25) ? expf(-sqrtf((float)d2)) : 0.f;
    }

    // Compatibility matrix in registers (uniform).
    const float c00 = __ldg(comp + 0), c01 = __ldg(comp + 1), c02 = __ldg(comp + 2);
    const float c10 = __ldg(comp + 3), c11 = __ldg(comp + 4), c12 = __ldg(comp + 5);
    const float c20 = __ldg(comp + 6), c21 = __ldg(comp + 7), c22 = __ldg(comp + 8);

    // This pixel's unary logits (epilogue threads only).
    float u0 = 0.f, u1 = 0.f, u2 = 0.f;
    if (ty == 0) {
        u0 = __ldg(unary + n);
        u1 = __ldg(unary + NPIX + n);
        u2 = __ldg(unary + 2 * NPIX + n);
    }
    __syncthreads();
    const unsigned base = s_base;

    for (int it = 0; it < NITER; it++) {
        // ---- wait for the 10 neighbor rows to finish iteration it-1 ----
        if (it > 0 && tid < 2 * HALO + 1 && tid != HALO) {
            const int z = y + tid - HALO;
            if (z >= 0 && z < HH) {
                const unsigned need = base + (unsigned)it;
                const unsigned* f = &g_done[z * FLAG_STRIDE];
                while (ld_flag(f) < need) { __nanosleep(32); }
            }
        }
        __syncthreads();

        // ---- halo fill (zero-padded outside the image) ----
        const float4* __restrict__ qsrc = g_q[(it + 1) & 1];
        for (int i = tid; i < SROWS * TW; i += TPB) {
            const int r  = i / TW;
            const int cc = i - r * TW;
            const int gy = y - HALO + r;
            const int gx = cc - HALO;
            float4 v = make_float4(0.f, 0.f, 0.f, 0.f);
            if (gy >= 0 && gy < HH && gx >= 0 && gx < WW) {
                const int m = gy * WW + gx;
                if (it == 0) {
                    // q0 = softmax(unary) computed on the fly
                    const float a0 = __ldg(unary + m);
                    const float a1 = __ldg(unary + NPIX + m);
                    const float a2 = __ldg(unary + 2 * NPIX + m);
                    const float mx = fmaxf(a0, fmaxf(a1, a2));
                    const float e0 = expf(a0 - mx), e1 = expf(a1 - mx), e2 = expf(a2 - mx);
                    const float rs = 1.f / (e0 + e1 + e2);
                    v = make_float4(e0 * rs, e1 * rs, e2 * rs, 0.f);
                } else {
                    v = __ldcg(qsrc + m);   // L2-coherent (skip stale L1)
                }
            }
            s_q[i] = v;
        }
        __syncthreads();

        // ---- 80-tap stencil, split 4 ways across ty ----
        const int center = HALO * TW + (x + HALO);
        float m0 = 0.f, m1 = 0.f, m2 = 0.f;
        switch (ty) {
            case 0: accum<0>(s_q, s_w, center, m0, m1, m2); break;
            case 1: accum<1>(s_q, s_w, center, m0, m1, m2); break;
            case 2: accum<2>(s_q, s_w, center, m0, m1, m2); break;
            default: accum<3>(s_q, s_w, center, m0, m1, m2); break;
        }
        if (ty > 0) s_part[ty - 1][x] = make_float4(m0, m1, m2, 0.f);
        __syncthreads();

        // ---- epilogue: combine partials, compat mix, softmax, store ----
        if (ty == 0) {
            const float4 p0 = s_part[0][x];
            const float4 p1 = s_part[1][x];
            const float4 p2 = s_part[2][x];
            m0 += p0.x + p1.x + p2.x;
            m1 += p0.y + p1.y + p2.y;
            m2 += p0.z + p1.z + p2.z;

            const float cm0 = c00 * m0 + c01 * m1 + c02 * m2;
            const float cm1 = c10 * m0 + c11 * m1 + c12 * m2;
            const float cm2 = c20 * m0 + c21 * m1 + c22 * m2;

            const float l0 = u0 + cm0;
            const float l1 = u1 + cm1;
            const float l2 = u2 + cm2;

            const float mx = fmaxf(l0, fmaxf(l1, l2));
            float e0 = expf(l0 - mx), e1 = expf(l1 - mx), e2 = expf(l2 - mx);
            const float rs = 1.f / (e0 + e1 + e2);
            e0 *= rs; e1 *= rs; e2 *= rs;

            if (it == NITER - 1) {
                out[n]            = e0;
                out[NPIX + n]     = e1;
                out[2 * NPIX + n] = e2;
            } else {
                g_q[it & 1][n] = make_float4(e0, e1, e2, 0.f);
                __threadfence();   // release: publish this thread's q store
            }
        }

        if (it < NITER - 1) {
            __syncthreads();       // all release fences done before the flag
            if (tid == 0) {
                asm volatile("st.global.cg.u32 [%0], %1;"
                             :: "l"(&g_done[y * FLAG_STRIDE]),
                                "r"(base + (unsigned)(it + 1)) : "memory");
            }
        }
    }
}

extern "C" void kernel_launch(void* const* d_in, const int* in_sizes, int n_in,
                              void* d_out, int out_size)
{
    (void)in_sizes; (void)n_in; (void)out_size;
    const float* unary = (const float*)d_in[0];
    const float* comp  = (const float*)d_in[1];
    float* out = (float*)d_out;

    crf_all<<<NBLK, TPB>>>(unary, comp, out);
}